// round 13
// baseline (speedup 1.0000x reference)
#include <cuda_runtime.h>
#include <cuda_fp16.h>
#include <math.h>
#include <stdint.h>

// Problem constants
#define LYR 6
#define BB  4
#define SS  1024
#define DD  1024
#define HH  16
#define DKK 64
#define FF  4096
#define MM  (BB*SS)          // 4096 rows
#define ATT_SCALE 0.125f     // 1/sqrt(64)
#define LN_EPS 1e-6f

// ---------------- scratch buffers (device globals; no allocation) -------------
__device__ float  g_x [MM*DD];
__device__ float  g_h [MM*DD];
__device__ __half g_htf[MM*DD];     // fp16 LN output (GEMM A operand)
__device__ float  g_x1[MM*DD];
__device__ __half g_qkv[MM*3*DD];   // fused QKV output
__device__ __half g_o [MM*DD];      // attn out, fp16
__device__ __half g_ff[MM*FF];      // relu out, fp16
// pre-converted + TRANSPOSED weights: Bt[n][k] = fp16(W[k][n])
__device__ __half g_wqkvc[LYR*3*DD*DD];
__device__ __half g_woc[LYR*DD*DD];
__device__ __half g_w1c[LYR*DD*FF];
__device__ __half g_w2c[LYR*FF*DD];
__device__ float  g_bqkv[LYR*3*DD];

// ---------------- helpers ----------------
__device__ __forceinline__ void mma_f16(float c[4], const unsigned a[4], const unsigned b[2]) {
    asm volatile("mma.sync.aligned.m16n8k16.row.col.f32.f16.f16.f32 "
        "{%0,%1,%2,%3}, {%4,%5,%6,%7}, {%8,%9}, {%0,%1,%2,%3};"
        : "+f"(c[0]), "+f"(c[1]), "+f"(c[2]), "+f"(c[3])
        : "r"(a[0]), "r"(a[1]), "r"(a[2]), "r"(a[3]), "r"(b[0]), "r"(b[1]));
}

__device__ __forceinline__ void ldsm4(unsigned r[4], unsigned addr) {
    asm volatile("ldmatrix.sync.aligned.m8n8.x4.shared.b16 {%0,%1,%2,%3}, [%4];"
        : "=r"(r[0]), "=r"(r[1]), "=r"(r[2]), "=r"(r[3]) : "r"(addr));
}

__device__ __forceinline__ void ldsm4t(unsigned r[4], unsigned addr) {
    asm volatile("ldmatrix.sync.aligned.m8n8.x4.trans.shared.b16 {%0,%1,%2,%3}, [%4];"
        : "=r"(r[0]), "=r"(r[1]), "=r"(r[2]), "=r"(r[3]) : "r"(addr));
}

__device__ __forceinline__ void cp16(unsigned dst, const void* src) {
    asm volatile("cp.async.cg.shared.global [%0], [%1], 16;" :: "r"(dst), "l"(src));
}
__device__ __forceinline__ void cp4(unsigned dst, const void* src) {
    asm volatile("cp.async.ca.shared.global [%0], [%1], 4;" :: "r"(dst), "l"(src));
}
#define CP_COMMIT() asm volatile("cp.async.commit_group;" ::: "memory")
#define CP_WAIT2()  asm volatile("cp.async.wait_group 2;" ::: "memory")
#define CP_WAIT1()  asm volatile("cp.async.wait_group 1;" ::: "memory")

__device__ __forceinline__ unsigned packh2(float a, float b) {
    __half2 h = __floats2half2_rn(a, b);
    return *(unsigned*)&h;
}

// ---------------- weight prep: dst[n][k] = fp16(src[k][n]) -------------------
__global__ void h16conv_t_kernel(const float* __restrict__ src,
                                 __half* __restrict__ dst, int K, int N,
                                 size_t dstLayerStride, int rowOff)
{
    __shared__ float t[32][33];
    int l = blockIdx.z;
    const float* s = src + (size_t)l * K * N;
    __half* d = dst + (size_t)l * dstLayerStride + (size_t)rowOff * K;
    int n0 = blockIdx.x * 32, k0 = blockIdx.y * 32;
    int tx = threadIdx.x, ty = threadIdx.y;   // 32 x 8
    #pragma unroll
    for (int i = 0; i < 32; i += 8)
        t[ty + i][tx] = s[(size_t)(k0 + ty + i) * N + n0 + tx];
    __syncthreads();
    #pragma unroll
    for (int i = 0; i < 32; i += 8)
        d[(size_t)(n0 + ty + i) * K + k0 + tx] = __float2half_rn(t[tx][ty + i]);
}

// ---------------- bias concat for fused QKV ----------------------------------
__global__ void bias_cat_kernel(const float* __restrict__ bq,
                                const float* __restrict__ bk,
                                const float* __restrict__ bv,
                                float* __restrict__ out)
{
    int i = blockIdx.x * blockDim.x + threadIdx.x;
    if (i >= LYR * 3 * DD) return;
    int l = i / (3 * DD), j = i % (3 * DD);
    float v = (j < DD) ? bq[l * DD + j]
            : (j < 2 * DD) ? bk[l * DD + j - DD]
            : bv[l * DD + j - 2 * DD];
    out[i] = v;
}

// ---------------- PE add ----------------
__global__ void add_pe_kernel(const float* __restrict__ embed,
                              const float* __restrict__ pe,
                              float* __restrict__ x)
{
    int i = blockIdx.x * blockDim.x + threadIdx.x;
    const int TOT4 = MM * DD / 4;
    if (i >= TOT4) return;
    int pe4 = i % (SS * DD / 4);
    float4 e = ((const float4*)embed)[i];
    float4 p = ((const float4*)pe)[pe4];
    float4 r; r.x = e.x + p.x; r.y = e.y + p.y; r.z = e.z + p.z; r.w = e.w + p.w;
    ((float4*)x)[i] = r;
}

// ---------------- LayerNorm (dual output: fp32 + fp16) -----------------------
__global__ void ln_kernel(const float* __restrict__ x,
                          const float* __restrict__ g,
                          const float* __restrict__ beta,
                          float* __restrict__ y,
                          __half* __restrict__ ytf)
{
    __shared__ float shm[32];
    __shared__ float s_mu, s_rstd;
    int row = blockIdx.x;
    int t   = threadIdx.x;
    const float4* xr = (const float4*)(x + (size_t)row * DD);
    float4 v = xr[t];
    float s = v.x + v.y + v.z + v.w;
    #pragma unroll
    for (int o = 16; o; o >>= 1) s += __shfl_xor_sync(0xffffffffu, s, o);
    if ((t & 31) == 0) shm[t >> 5] = s;
    __syncthreads();
    if (t < 32) {
        float tot = (t < 8) ? shm[t] : 0.f;
        #pragma unroll
        for (int o = 4; o; o >>= 1) tot += __shfl_xor_sync(0xffffffffu, tot, o);
        if (t == 0) s_mu = tot * (1.0f / DD);
    }
    __syncthreads();
    float mu = s_mu;
    float d0 = v.x - mu, d1 = v.y - mu, d2 = v.z - mu, d3 = v.w - mu;
    float s2 = d0*d0 + d1*d1 + d2*d2 + d3*d3;
    #pragma unroll
    for (int o = 16; o; o >>= 1) s2 += __shfl_xor_sync(0xffffffffu, s2, o);
    if ((t & 31) == 0) shm[t >> 5] = s2;
    __syncthreads();
    if (t < 32) {
        float tot = (t < 8) ? shm[t] : 0.f;
        #pragma unroll
        for (int o = 4; o; o >>= 1) tot += __shfl_xor_sync(0xffffffffu, tot, o);
        if (t == 0) s_rstd = rsqrtf(tot * (1.0f / DD) + LN_EPS);
    }
    __syncthreads();
    float rstd = s_rstd;
    float4 gg = ((const float4*)g)[t];
    float4 bb = ((const float4*)beta)[t];
    float4 out;
    out.x = d0 * rstd * gg.x + bb.x;
    out.y = d1 * rstd * gg.y + bb.y;
    out.z = d2 * rstd * gg.z + bb.z;
    out.w = d3 * rstd * gg.w + bb.w;
    ((float4*)(y + (size_t)row * DD))[t] = out;
    if (ytf) {
        __half2* yh = (__half2*)(ytf + (size_t)row * DD);
        yh[2*t    ] = __floats2half2_rn(out.x, out.y);
        yh[2*t + 1] = __floats2half2_rn(out.z, out.w);
    }
}

// ---------------- FP16 GEMM 128x256 (mma m16n8k16), 4-stage cp.async ---------
// C[M,N] = A[M,K] @ Bt[N,K]^T.  512 threads = 16 warps (2 M x 8 N),
// warp tile 64x32 (identical per-warp structure to the 128x128 version ->
// bit-identical accumulation chains).
#define BM 128
#define BN 256
#define BKH 32
#define STAGES 4
#define STRH 40
#define A_STG (BM*STRH)      // halfs per stage
#define B_STG (BN*STRH)
#define GEMM_SMEM_BYTES (STAGES * (A_STG + B_STG) * 2)   // 122880

__global__ __launch_bounds__(512, 1)
void mma_gemm_kernel(const __half* __restrict__ A, const __half* __restrict__ Bt,
                     const float* __restrict__ bias, const float* __restrict__ res,
                     const int* __restrict__ mask, void* __restrict__ Cv,
                     int M, int N, int K, int epi)
{
    extern __shared__ __half smemh[];
    __half* Asm = smemh;
    __half* Bsm = smemh + STAGES * A_STG;
    const unsigned a_u = (unsigned)__cvta_generic_to_shared(Asm);
    const unsigned b_u = (unsigned)__cvta_generic_to_shared(Bsm);

    const int tid  = threadIdx.x;
    const int lane = tid & 31;
    const int wrp  = tid >> 5;       // 0..15
    const int wm   = wrp >> 3;       // 0..1 -> 64 rows
    const int wn   = wrp & 7;        // 0..7 -> 32 cols
    const int l15  = lane & 15;
    const int lhi  = lane >> 4;
    const int g    = lane >> 2;
    const int cc   = lane & 3;

    const int brow = blockIdx.y * BM;
    const int bcol = blockIdx.x * BN;

    // staging: B by all 512 threads (row tid>>1 of 256), A by threads <256
    const int s_r = tid >> 1, s_c = (tid & 1) * 16;
    const __half* Ag = A  + (size_t)(brow + s_r) * K + s_c;   // valid for tid<256
    const __half* Bg = Bt + (size_t)(bcol + s_r) * K + s_c;

    const int NK = K / BKH;

    auto load_stage = [&](int s, int kt) {
        const __half* bg = Bg + kt * BKH;
        unsigned db = (unsigned)((s * B_STG + s_r * STRH + s_c) * 2);
        cp16(b_u + db, bg); cp16(b_u + db + 16, bg + 8);
        if (tid < 256) {
            const __half* ag = Ag + kt * BKH;
            unsigned da = (unsigned)((s * A_STG + s_r * STRH + s_c) * 2);
            cp16(a_u + da, ag); cp16(a_u + da + 16, ag + 8);
        }
    };

    float acc[4][4][4];
    #pragma unroll
    for (int i = 0; i < 4; i++)
        #pragma unroll
        for (int j = 0; j < 4; j++) {
            acc[i][j][0] = 0.f; acc[i][j][1] = 0.f;
            acc[i][j][2] = 0.f; acc[i][j][3] = 0.f;
        }

    load_stage(0, 0); CP_COMMIT();
    load_stage(1, 1); CP_COMMIT();
    load_stage(2, 2); CP_COMMIT();

    const unsigned a_frag_off = (unsigned)(((wm * 64 + l15) * STRH + lhi * 8) * 2);
    const unsigned b_frag_off = (unsigned)(((wn * 32 + l15) * STRH + lhi * 8) * 2);

    int cur = 0;
    for (int kt = 0; kt < NK; kt++) {
        CP_WAIT2();
        __syncthreads();

        if (kt + 3 < NK) load_stage((kt + 3) & 3, kt + 3);
        CP_COMMIT();

        const unsigned abase = a_u + (unsigned)(cur * A_STG * 2) + a_frag_off;
        const unsigned bbase = b_u + (unsigned)(cur * B_STG * 2) + b_frag_off;

        #pragma unroll
        for (int ks = 0; ks < 2; ks++) {
            unsigned a[4][4], b[2][4];
            #pragma unroll
            for (int mt = 0; mt < 4; mt++)
                ldsm4(a[mt], abase + (unsigned)(mt * 16 * STRH * 2 + ks * 32));
            #pragma unroll
            for (int bt = 0; bt < 2; bt++)
                ldsm4(b[bt], bbase + (unsigned)(bt * 16 * STRH * 2 + ks * 32));

            #pragma unroll
            for (int mt = 0; mt < 4; mt++) {
                {   unsigned bf[2] = { b[0][0], b[0][2] };
                    mma_f16(acc[mt][0], a[mt], bf); }
                {   unsigned bf[2] = { b[0][1], b[0][3] };
                    mma_f16(acc[mt][1], a[mt], bf); }
                {   unsigned bf[2] = { b[1][0], b[1][2] };
                    mma_f16(acc[mt][2], a[mt], bf); }
                {   unsigned bf[2] = { b[1][1], b[1][3] };
                    mma_f16(acc[mt][3], a[mt], bf); }
            }
        }
        cur = (cur + 1) & 3;
    }

    // ---- epilogue ----
    #pragma unroll
    for (int mt = 0; mt < 4; mt++) {
        int r0 = brow + wm * 64 + mt * 16 + g;
        int r1 = r0 + 8;
        float mk0 = 1.f, mk1 = 1.f;
        if (epi == 2) {
            mk0 = mask[r0] ? 1.f : 0.f;
            mk1 = mask[r1] ? 1.f : 0.f;
        }
        #pragma unroll
        for (int nt = 0; nt < 4; nt++) {
            int ncol = bcol + wn * 32 + nt * 8 + cc * 2;
            float2 bv = *(const float2*)(bias + ncol);
            float2 o0, o1;
            o0.x = acc[mt][nt][0] + bv.x; o0.y = acc[mt][nt][1] + bv.y;
            o1.x = acc[mt][nt][2] + bv.x; o1.y = acc[mt][nt][3] + bv.y;
            if (epi == 0) {
                __half* Ch = (__half*)Cv;
                *(__half2*)(Ch + (size_t)r0 * N + ncol) = __floats2half2_rn(o0.x, o0.y);
                *(__half2*)(Ch + (size_t)r1 * N + ncol) = __floats2half2_rn(o1.x, o1.y);
            } else if (epi == 1) {
                __half* Ch = (__half*)Cv;
                *(__half2*)(Ch + (size_t)r0 * N + ncol) =
                    __floats2half2_rn(fmaxf(o0.x, 0.f), fmaxf(o0.y, 0.f));
                *(__half2*)(Ch + (size_t)r1 * N + ncol) =
                    __floats2half2_rn(fmaxf(o1.x, 0.f), fmaxf(o1.y, 0.f));
            } else {
                float* Cf = (float*)Cv;
                float2 rv0 = *(const float2*)(res + (size_t)r0 * N + ncol);
                float2 rv1 = *(const float2*)(res + (size_t)r1 * N + ncol);
                o0.x = (o0.x + rv0.x) * mk0; o0.y = (o0.y + rv0.y) * mk0;
                o1.x = (o1.x + rv1.x) * mk1; o1.y = (o1.y + rv1.y) * mk1;
                *(float2*)(Cf + (size_t)r0 * N + ncol) = o0;
                *(float2*)(Cf + (size_t)r1 * N + ncol) = o1;
            }
        }
    }
}

// ---------------- FP16 flash attention (mma m16n8k16, ldsm.trans V) ----------
#define AQT 64
#define AKT 32
#define KSTR 72

__global__ __launch_bounds__(128)
void attn_f16_kernel(const __half* __restrict__ QKV, const int* __restrict__ npm,
                     __half* __restrict__ O)
{
    __shared__ __half Qs[AQT][KSTR];
    __shared__ __half Ks[2][AKT][KSTR];
    __shared__ __half Vs[2][AKT][KSTR];
    __shared__ int kmsi[2][AKT];

    const unsigned q_u = (unsigned)__cvta_generic_to_shared(Qs);
    const unsigned k_u = (unsigned)__cvta_generic_to_shared(Ks);
    const unsigned v_u = (unsigned)__cvta_generic_to_shared(Vs);
    const unsigned m_u = (unsigned)__cvta_generic_to_shared(kmsi);

    const int b = blockIdx.z, h = blockIdx.y, qt = blockIdx.x;
    const int tid  = threadIdx.x;
    const int lane = tid & 31;
    const int wq   = tid >> 5;
    const int g    = lane >> 2;
    const int cc   = lane & 3;
    const int l15  = lane & 15;
    const int lhi  = lane >> 4;
    const int wr   = wq * 16;

    const int RS = 3 * DD;
    const __half* Qbase = QKV + (size_t)(b * SS + qt * AQT) * RS + h * 64;
    const __half* Kb0   = QKV + (size_t)(b * SS) * RS + DD + h * 64;
    const __half* Vb0   = QKV + (size_t)(b * SS) * RS + 2 * DD + h * 64;

    #pragma unroll
    for (int i = tid; i < AQT * 8; i += 128) {
        int r = i >> 3, c = (i & 7) * 8;
        cp16(q_u + (unsigned)((r * KSTR + c) * 2), Qbase + (size_t)r * RS + c);
    }
    CP_COMMIT();

    auto load_kv = [&](int s, int kt) {
        const __half* kp = Kb0 + (size_t)(kt * AKT) * RS;
        const __half* vp = Vb0 + (size_t)(kt * AKT) * RS;
        #pragma unroll
        for (int i = tid; i < AKT * 8; i += 128) {
            int r = i >> 3, c = (i & 7) * 8;
            cp16(k_u + (unsigned)(((s * AKT + r) * KSTR + c) * 2), kp + (size_t)r * RS + c);
            cp16(v_u + (unsigned)(((s * AKT + r) * KSTR + c) * 2), vp + (size_t)r * RS + c);
        }
        if (tid < AKT) cp4(m_u + (unsigned)((s * AKT + tid) * 4),
                           npm + b * SS + kt * AKT + tid);
    };

    load_kv(0, 0); CP_COMMIT();

    float m0 = -1e30f, m1 = -1e30f, l0 = 0.f, l1 = 0.f;
    float o[8][4];
    #pragma unroll
    for (int nt = 0; nt < 8; nt++) {
        o[nt][0] = 0.f; o[nt][1] = 0.f; o[nt][2] = 0.f; o[nt][3] = 0.f;
    }

    const unsigned qf_off = (unsigned)(((wr + l15) * KSTR + lhi * 8) * 2);
    const int NKT = SS / AKT;

    for (int kt = 0; kt < NKT; kt++) {
        int st = kt & 1;
        if (kt + 1 < NKT) load_kv(st ^ 1, kt + 1);
        CP_COMMIT();
        CP_WAIT1();
        __syncthreads();

        float s[4][4];
        #pragma unroll
        for (int nt = 0; nt < 4; nt++) {
            s[nt][0] = 0.f; s[nt][1] = 0.f; s[nt][2] = 0.f; s[nt][3] = 0.f;
        }
        #pragma unroll
        for (int ks = 0; ks < 4; ks++) {
            unsigned a[4];
            ldsm4(a, q_u + qf_off + (unsigned)(ks * 32));
            #pragma unroll
            for (int bt = 0; bt < 2; bt++) {
                unsigned bfr[4];
                ldsm4(bfr, k_u + (unsigned)((((st * AKT + bt * 16 + l15) * KSTR + lhi * 8) * 2 + ks * 32)));
                {   unsigned bf[2] = { bfr[0], bfr[2] };
                    mma_f16(s[bt*2    ], a, bf); }
                {   unsigned bf[2] = { bfr[1], bfr[3] };
                    mma_f16(s[bt*2 + 1], a, bf); }
            }
        }

        #pragma unroll
        for (int nt = 0; nt < 4; nt++) {
            int k0i = kmsi[st][nt*8 + 2*cc];
            int k1i = kmsi[st][nt*8 + 2*cc + 1];
            s[nt][0] = k0i ? s[nt][0] * ATT_SCALE : -1e9f;
            s[nt][1] = k1i ? s[nt][1] * ATT_SCALE : -1e9f;
            s[nt][2] = k0i ? s[nt][2] * ATT_SCALE : -1e9f;
            s[nt][3] = k1i ? s[nt][3] * ATT_SCALE : -1e9f;
        }

        float tm0 = s[0][0], tm1 = s[0][2];
        #pragma unroll
        for (int nt = 0; nt < 4; nt++) {
            tm0 = fmaxf(tm0, fmaxf(s[nt][0], s[nt][1]));
            tm1 = fmaxf(tm1, fmaxf(s[nt][2], s[nt][3]));
        }
        tm0 = fmaxf(tm0, __shfl_xor_sync(0xffffffffu, tm0, 1));
        tm0 = fmaxf(tm0, __shfl_xor_sync(0xffffffffu, tm0, 2));
        tm1 = fmaxf(tm1, __shfl_xor_sync(0xffffffffu, tm1, 1));
        tm1 = fmaxf(tm1, __shfl_xor_sync(0xffffffffu, tm1, 2));
        float nm0 = fmaxf(m0, tm0), nm1 = fmaxf(m1, tm1);
        float f0 = __expf(m0 - nm0), f1 = __expf(m1 - nm1);

        float sum0 = 0.f, sum1 = 0.f;
        unsigned ap[2][4];
        #pragma unroll
        for (int nt = 0; nt < 4; nt++) {
            float p0 = __expf(s[nt][0] - nm0);
            float p1 = __expf(s[nt][1] - nm0);
            float p2 = __expf(s[nt][2] - nm1);
            float p3 = __expf(s[nt][3] - nm1);
            sum0 += p0 + p1;
            sum1 += p2 + p3;
            int ks = nt >> 1, hi = (nt & 1) * 2;
            ap[ks][hi    ] = packh2(p0, p1);
            ap[ks][hi + 1] = packh2(p2, p3);
        }
        sum0 += __shfl_xor_sync(0xffffffffu, sum0, 1);
        sum0 += __shfl_xor_sync(0xffffffffu, sum0, 2);
        sum1 += __shfl_xor_sync(0xffffffffu, sum1, 1);
        sum1 += __shfl_xor_sync(0xffffffffu, sum1, 2);
        l0 = l0 * f0 + sum0;
        l1 = l1 * f1 + sum1;
        m0 = nm0; m1 = nm1;

        #pragma unroll
        for (int nt = 0; nt < 8; nt++) {
            o[nt][0] *= f0; o[nt][1] *= f0;
            o[nt][2] *= f1; o[nt][3] *= f1;
        }

        #pragma unroll
        for (int ks = 0; ks < 2; ks++) {
            #pragma unroll
            for (int dkc = 0; dkc < 4; dkc++) {
                unsigned bfr[4];
                ldsm4t(bfr, v_u + (unsigned)((((st * AKT + ks * 16 + l15) * KSTR
                                               + dkc * 16 + lhi * 8) * 2)));
                {   unsigned bf[2] = { bfr[0], bfr[1] };
                    mma_f16(o[dkc*2    ], ap[ks], bf); }
                {   unsigned bf[2] = { bfr[2], bfr[3] };
                    mma_f16(o[dkc*2 + 1], ap[ks], bf); }
            }
        }
        __syncthreads();
    }

    float i0 = 1.f / l0, i1 = 1.f / l1;
    size_t r0 = (size_t)(b * SS + qt * AQT + wr + g) * DD + h * 64;
    size_t r1 = r0 + (size_t)8 * DD;
    #pragma unroll
    for (int nt = 0; nt < 8; nt++) {
        int ncol = nt * 8 + 2 * cc;
        *(__half2*)(O + r0 + ncol) = __floats2half2_rn(o[nt][0] * i0, o[nt][1] * i0);
        *(__half2*)(O + r1 + ncol) = __floats2half2_rn(o[nt][2] * i1, o[nt][3] * i1);
    }
}

// ---------------- host orchestration ----------------
extern "C" void kernel_launch(void* const* d_in, const int* in_sizes, int n_in,
                              void* d_out, int out_size)
{
    const float* embed = (const float*)d_in[0];
    const int*   npm   = (const int*)  d_in[1];
    const float* pe    = (const float*)d_in[2];
    const float* Wq    = (const float*)d_in[3];
    const float* bq    = (const float*)d_in[4];
    const float* Wk    = (const float*)d_in[5];
    const float* bk    = (const float*)d_in[6];
    const float* Wv    = (const float*)d_in[7];
    const float* bv    = (const float*)d_in[8];
    const float* Wo    = (const float*)d_in[9];
    const float* bo    = (const float*)d_in[10];
    const float* ln1g  = (const float*)d_in[11];
    const float* ln1b  = (const float*)d_in[12];
    const float* W1    = (const float*)d_in[13];
    const float* b1    = (const float*)d_in[14];
    const float* W2    = (const float*)d_in[15];
    const float* b2    = (const float*)d_in[16];
    const float* ln2g  = (const float*)d_in[17];
    const float* ln2b  = (const float*)d_in[18];
    const float* lnfg  = (const float*)d_in[19];
    const float* lnfb  = (const float*)d_in[20];

    float *x, *hh, *x1, *bqkv;
    __half *htf, *qkv, *ob, *ffb;
    __half *wqkvc, *woc, *w1c, *w2c;
    cudaGetSymbolAddress((void**)&x,    g_x);
    cudaGetSymbolAddress((void**)&hh,   g_h);
    cudaGetSymbolAddress((void**)&htf,  g_htf);
    cudaGetSymbolAddress((void**)&x1,   g_x1);
    cudaGetSymbolAddress((void**)&qkv,  g_qkv);
    cudaGetSymbolAddress((void**)&ob,   g_o);
    cudaGetSymbolAddress((void**)&ffb,  g_ff);
    cudaGetSymbolAddress((void**)&wqkvc, g_wqkvc);
    cudaGetSymbolAddress((void**)&woc,  g_woc);
    cudaGetSymbolAddress((void**)&w1c,  g_w1c);
    cudaGetSymbolAddress((void**)&w2c,  g_w2c);
    cudaGetSymbolAddress((void**)&bqkv, g_bqkv);

    cudaFuncSetAttribute(mma_gemm_kernel,
                         cudaFuncAttributeMaxDynamicSharedMemorySize,
                         GEMM_SMEM_BYTES);

    // weight prep
    {
        dim3 blk(32, 8);
        size_t qkvLS = (size_t)3 * DD * DD;
        h16conv_t_kernel<<<dim3(DD/32, DD/32, LYR), blk>>>(Wq, wqkvc, DD, DD, qkvLS, 0);
        h16conv_t_kernel<<<dim3(DD/32, DD/32, LYR), blk>>>(Wk, wqkvc, DD, DD, qkvLS, DD);
        h16conv_t_kernel<<<dim3(DD/32, DD/32, LYR), blk>>>(Wv, wqkvc, DD, DD, qkvLS, 2*DD);
        h16conv_t_kernel<<<dim3(DD/32, DD/32, LYR), blk>>>(Wo, woc, DD, DD, (size_t)DD*DD, 0);
        h16conv_t_kernel<<<dim3(FF/32, DD/32, LYR), blk>>>(W1, w1c, DD, FF, (size_t)DD*FF, 0);
        h16conv_t_kernel<<<dim3(DD/32, FF/32, LYR), blk>>>(W2, w2c, FF, DD, (size_t)FF*DD, 0);
        int nb = LYR * 3 * DD;
        bias_cat_kernel<<<(nb + 255) / 256, 256>>>(bq, bk, bv, bqkv);
    }

    {
        int tot4 = MM * DD / 4;
        add_pe_kernel<<<(tot4 + 255) / 256, 256>>>(embed, pe, x);
    }

    dim3 gQKV(3 * DD / BN, MM / BM);  // (12, 32)
    dim3 gD(DD / BN, MM / BM);        // (4, 32)
    dim3 gF(FF / BN, MM / BM);        // (16, 32)
    dim3 gAttn(SS / AQT, HH, BB);     // (16, 16, 4)

    for (int l = 0; l < LYR; l++) {
        const __half* wqkv_l = wqkvc + (size_t)l * 3 * DD * DD;
        const __half* wo = woc + (size_t)l * DD * DD;
        const __half* w1 = w1c + (size_t)l * DD * FF;
        const __half* w2 = w2c + (size_t)l * FF * DD;
        const float* lbqkv = bqkv + (size_t)l * 3 * DD;
        const float* lbo = bo + (size_t)l * DD;
        const float* lb1 = b1 + (size_t)l * FF;
        const float* lb2 = b2 + (size_t)l * DD;

        ln_kernel<<<MM, 256>>>(x, ln1g + (size_t)l * DD, ln1b + (size_t)l * DD, hh, htf);
        mma_gemm_kernel<<<gQKV, 512, GEMM_SMEM_BYTES>>>(htf, wqkv_l, lbqkv, nullptr, nullptr, qkv, MM, 3*DD, DD, 0);
        attn_f16_kernel<<<gAttn, 128>>>(qkv, npm, ob);
        mma_gemm_kernel<<<gD, 512, GEMM_SMEM_BYTES>>>(ob, wo, lbo, hh, npm, x1, MM, DD, DD, 2);
        ln_kernel<<<MM, 256>>>(x1, ln2g + (size_t)l * DD, ln2b + (size_t)l * DD, hh, htf);
        mma_gemm_kernel<<<gF, 512, GEMM_SMEM_BYTES>>>(htf, w1, lb1, nullptr, nullptr, ffb, MM, FF, DD, 1);
        mma_gemm_kernel<<<gD, 512, GEMM_SMEM_BYTES>>>(ffb, w2, lb2, hh, npm, x, MM, DD, FF, 2);
    }

    ln_kernel<<<MM, 256>>>(x, lnfg, lnfb, (float*)d_out, nullptr);
}

// round 14
// speedup vs baseline: 1.0091x; 1.0091x over previous
#include <cuda_runtime.h>
#include <cuda_fp16.h>
#include <math.h>
#include <stdint.h>

// Problem constants
#define LYR 6
#define BB  4
#define SS  1024
#define DD  1024
#define HH  16
#define DKK 64
#define FF  4096
#define MM  (BB*SS)          // 4096 rows
#define ATT_SCALE 0.125f     // 1/sqrt(64)
#define LN_EPS 1e-6f

// ---------------- scratch buffers (device globals; no allocation) -------------
__device__ float  g_x [MM*DD];
__device__ float  g_h [MM*DD];
__device__ __half g_htf[MM*DD];     // fp16 LN output (GEMM A operand)
__device__ float  g_x1[MM*DD];
__device__ __half g_qkv[MM*3*DD];   // fused QKV output
__device__ __half g_o [MM*DD];      // attn out, fp16
__device__ __half g_ff[MM*FF];      // relu out, fp16
// pre-converted + TRANSPOSED weights: Bt[n][k] = fp16(W[k][n])
__device__ __half g_wqkvc[LYR*3*DD*DD];
__device__ __half g_woc[LYR*DD*DD];
__device__ __half g_w1c[LYR*DD*FF];
__device__ __half g_w2c[LYR*FF*DD];
__device__ float  g_bqkv[LYR*3*DD];

// ---------------- helpers ----------------
__device__ __forceinline__ void mma_f16(float c[4], const unsigned a[4], const unsigned b[2]) {
    asm volatile("mma.sync.aligned.m16n8k16.row.col.f32.f16.f16.f32 "
        "{%0,%1,%2,%3}, {%4,%5,%6,%7}, {%8,%9}, {%0,%1,%2,%3};"
        : "+f"(c[0]), "+f"(c[1]), "+f"(c[2]), "+f"(c[3])
        : "r"(a[0]), "r"(a[1]), "r"(a[2]), "r"(a[3]), "r"(b[0]), "r"(b[1]));
}

__device__ __forceinline__ void ldsm4(unsigned r[4], unsigned addr) {
    asm volatile("ldmatrix.sync.aligned.m8n8.x4.shared.b16 {%0,%1,%2,%3}, [%4];"
        : "=r"(r[0]), "=r"(r[1]), "=r"(r[2]), "=r"(r[3]) : "r"(addr));
}

__device__ __forceinline__ void ldsm4t(unsigned r[4], unsigned addr) {
    asm volatile("ldmatrix.sync.aligned.m8n8.x4.trans.shared.b16 {%0,%1,%2,%3}, [%4];"
        : "=r"(r[0]), "=r"(r[1]), "=r"(r[2]), "=r"(r[3]) : "r"(addr));
}

__device__ __forceinline__ void cp16(unsigned dst, const void* src) {
    asm volatile("cp.async.cg.shared.global [%0], [%1], 16;" :: "r"(dst), "l"(src));
}
__device__ __forceinline__ void cp4(unsigned dst, const void* src) {
    asm volatile("cp.async.ca.shared.global [%0], [%1], 4;" :: "r"(dst), "l"(src));
}
#define CP_COMMIT() asm volatile("cp.async.commit_group;" ::: "memory")
#define CP_WAIT2()  asm volatile("cp.async.wait_group 2;" ::: "memory")
#define CP_WAIT1()  asm volatile("cp.async.wait_group 1;" ::: "memory")

__device__ __forceinline__ unsigned packh2(float a, float b) {
    __half2 h = __floats2half2_rn(a, b);
    return *(unsigned*)&h;
}

// ---------------- weight prep: dst[n][k] = fp16(src[k][n]) -------------------
__global__ void h16conv_t_kernel(const float* __restrict__ src,
                                 __half* __restrict__ dst, int K, int N,
                                 size_t dstLayerStride, int rowOff)
{
    __shared__ float t[32][33];
    int l = blockIdx.z;
    const float* s = src + (size_t)l * K * N;
    __half* d = dst + (size_t)l * dstLayerStride + (size_t)rowOff * K;
    int n0 = blockIdx.x * 32, k0 = blockIdx.y * 32;
    int tx = threadIdx.x, ty = threadIdx.y;   // 32 x 8
    #pragma unroll
    for (int i = 0; i < 32; i += 8)
        t[ty + i][tx] = s[(size_t)(k0 + ty + i) * N + n0 + tx];
    __syncthreads();
    #pragma unroll
    for (int i = 0; i < 32; i += 8)
        d[(size_t)(n0 + ty + i) * K + k0 + tx] = __float2half_rn(t[tx][ty + i]);
}

// ---------------- bias concat for fused QKV ----------------------------------
__global__ void bias_cat_kernel(const float* __restrict__ bq,
                                const float* __restrict__ bk,
                                const float* __restrict__ bv,
                                float* __restrict__ out)
{
    int i = blockIdx.x * blockDim.x + threadIdx.x;
    if (i >= LYR * 3 * DD) return;
    int l = i / (3 * DD), j = i % (3 * DD);
    float v = (j < DD) ? bq[l * DD + j]
            : (j < 2 * DD) ? bk[l * DD + j - DD]
            : bv[l * DD + j - 2 * DD];
    out[i] = v;
}

// ---------------- PE add ----------------
__global__ void add_pe_kernel(const float* __restrict__ embed,
                              const float* __restrict__ pe,
                              float* __restrict__ x)
{
    int i = blockIdx.x * blockDim.x + threadIdx.x;
    const int TOT4 = MM * DD / 4;
    if (i >= TOT4) return;
    int pe4 = i % (SS * DD / 4);
    float4 e = ((const float4*)embed)[i];
    float4 p = ((const float4*)pe)[pe4];
    float4 r; r.x = e.x + p.x; r.y = e.y + p.y; r.z = e.z + p.z; r.w = e.w + p.w;
    ((float4*)x)[i] = r;
}

// ---------------- LayerNorm (dual output: fp32 + fp16) -----------------------
__global__ void ln_kernel(const float* __restrict__ x,
                          const float* __restrict__ g,
                          const float* __restrict__ beta,
                          float* __restrict__ y,
                          __half* __restrict__ ytf)
{
    __shared__ float shm[32];
    __shared__ float s_mu, s_rstd;
    int row = blockIdx.x;
    int t   = threadIdx.x;
    const float4* xr = (const float4*)(x + (size_t)row * DD);
    float4 v = xr[t];
    float s = v.x + v.y + v.z + v.w;
    #pragma unroll
    for (int o = 16; o; o >>= 1) s += __shfl_xor_sync(0xffffffffu, s, o);
    if ((t & 31) == 0) shm[t >> 5] = s;
    __syncthreads();
    if (t < 32) {
        float tot = (t < 8) ? shm[t] : 0.f;
        #pragma unroll
        for (int o = 4; o; o >>= 1) tot += __shfl_xor_sync(0xffffffffu, tot, o);
        if (t == 0) s_mu = tot * (1.0f / DD);
    }
    __syncthreads();
    float mu = s_mu;
    float d0 = v.x - mu, d1 = v.y - mu, d2 = v.z - mu, d3 = v.w - mu;
    float s2 = d0*d0 + d1*d1 + d2*d2 + d3*d3;
    #pragma unroll
    for (int o = 16; o; o >>= 1) s2 += __shfl_xor_sync(0xffffffffu, s2, o);
    if ((t & 31) == 0) shm[t >> 5] = s2;
    __syncthreads();
    if (t < 32) {
        float tot = (t < 8) ? shm[t] : 0.f;
        #pragma unroll
        for (int o = 4; o; o >>= 1) tot += __shfl_xor_sync(0xffffffffu, tot, o);
        if (t == 0) s_rstd = rsqrtf(tot * (1.0f / DD) + LN_EPS);
    }
    __syncthreads();
    float rstd = s_rstd;
    float4 gg = ((const float4*)g)[t];
    float4 bb = ((const float4*)beta)[t];
    float4 out;
    out.x = d0 * rstd * gg.x + bb.x;
    out.y = d1 * rstd * gg.y + bb.y;
    out.z = d2 * rstd * gg.z + bb.z;
    out.w = d3 * rstd * gg.w + bb.w;
    ((float4*)(y + (size_t)row * DD))[t] = out;
    if (ytf) {
        __half2* yh = (__half2*)(ytf + (size_t)row * DD);
        yh[2*t    ] = __floats2half2_rn(out.x, out.y);
        yh[2*t + 1] = __floats2half2_rn(out.z, out.w);
    }
}

// ---------------- FP16 GEMM 128x128 (mma m16n8k16), 4-stage cp.async ---------
// (reverted to the R12 winner: 256 threads, 2 CTAs/SM)
#define BM 128
#define BN 128
#define BKH 32
#define STAGES 4
#define STRH 40
#define T_STG (BM*STRH)
#define GEMM_SMEM_BYTES (STAGES * 2 * T_STG * 2)   // 81920

__global__ __launch_bounds__(256, 2)
void mma_gemm_kernel(const __half* __restrict__ A, const __half* __restrict__ Bt,
                     const float* __restrict__ bias, const float* __restrict__ res,
                     const int* __restrict__ mask, void* __restrict__ Cv,
                     int M, int N, int K, int epi)
{
    extern __shared__ __half smemh[];
    __half* Asm = smemh;
    __half* Bsm = smemh + STAGES * T_STG;
    const unsigned a_u = (unsigned)__cvta_generic_to_shared(Asm);
    const unsigned b_u = (unsigned)__cvta_generic_to_shared(Bsm);

    const int tid  = threadIdx.x;
    const int lane = tid & 31;
    const int wrp  = tid >> 5;
    const int wm   = wrp >> 2;
    const int wn   = wrp & 3;
    const int l15  = lane & 15;
    const int lhi  = lane >> 4;
    const int g    = lane >> 2;
    const int cc   = lane & 3;

    const int brow = blockIdx.y * BM;
    const int bcol = blockIdx.x * BN;

    const int s_r = tid >> 1, s_c = (tid & 1) * 16;
    const __half* Ag = A  + (size_t)(brow + s_r) * K + s_c;
    const __half* Bg = Bt + (size_t)(bcol + s_r) * K + s_c;

    const int NK = K / BKH;

    auto load_stage = [&](int s, int kt) {
        const __half* ag = Ag + kt * BKH;
        const __half* bg = Bg + kt * BKH;
        unsigned d = (unsigned)((s * T_STG + s_r * STRH + s_c) * 2);
        cp16(a_u + d, ag); cp16(a_u + d + 16, ag + 8);
        cp16(b_u + d, bg); cp16(b_u + d + 16, bg + 8);
    };

    float acc[4][4][4];
    #pragma unroll
    for (int i = 0; i < 4; i++)
        #pragma unroll
        for (int j = 0; j < 4; j++) {
            acc[i][j][0] = 0.f; acc[i][j][1] = 0.f;
            acc[i][j][2] = 0.f; acc[i][j][3] = 0.f;
        }

    load_stage(0, 0); CP_COMMIT();
    load_stage(1, 1); CP_COMMIT();
    load_stage(2, 2); CP_COMMIT();

    const unsigned a_frag_off = (unsigned)(((wm * 64 + l15) * STRH + lhi * 8) * 2);
    const unsigned b_frag_off = (unsigned)(((wn * 32 + l15) * STRH + lhi * 8) * 2);

    int cur = 0;
    for (int kt = 0; kt < NK; kt++) {
        CP_WAIT2();
        __syncthreads();

        if (kt + 3 < NK) load_stage((kt + 3) & 3, kt + 3);
        CP_COMMIT();

        const unsigned abase = a_u + (unsigned)(cur * T_STG * 2) + a_frag_off;
        const unsigned bbase = b_u + (unsigned)(cur * T_STG * 2) + b_frag_off;

        #pragma unroll
        for (int ks = 0; ks < 2; ks++) {
            unsigned a[4][4], b[2][4];
            #pragma unroll
            for (int mt = 0; mt < 4; mt++)
                ldsm4(a[mt], abase + (unsigned)(mt * 16 * STRH * 2 + ks * 32));
            #pragma unroll
            for (int bt = 0; bt < 2; bt++)
                ldsm4(b[bt], bbase + (unsigned)(bt * 16 * STRH * 2 + ks * 32));

            #pragma unroll
            for (int mt = 0; mt < 4; mt++) {
                {   unsigned bf[2] = { b[0][0], b[0][2] };
                    mma_f16(acc[mt][0], a[mt], bf); }
                {   unsigned bf[2] = { b[0][1], b[0][3] };
                    mma_f16(acc[mt][1], a[mt], bf); }
                {   unsigned bf[2] = { b[1][0], b[1][2] };
                    mma_f16(acc[mt][2], a[mt], bf); }
                {   unsigned bf[2] = { b[1][1], b[1][3] };
                    mma_f16(acc[mt][3], a[mt], bf); }
            }
        }
        cur = (cur + 1) & 3;
    }

    // ---- epilogue ----
    #pragma unroll
    for (int mt = 0; mt < 4; mt++) {
        int r0 = brow + wm * 64 + mt * 16 + g;
        int r1 = r0 + 8;
        float mk0 = 1.f, mk1 = 1.f;
        if (epi == 2) {
            mk0 = mask[r0] ? 1.f : 0.f;
            mk1 = mask[r1] ? 1.f : 0.f;
        }
        #pragma unroll
        for (int nt = 0; nt < 4; nt++) {
            int ncol = bcol + wn * 32 + nt * 8 + cc * 2;
            float2 bv = *(const float2*)(bias + ncol);
            float2 o0, o1;
            o0.x = acc[mt][nt][0] + bv.x; o0.y = acc[mt][nt][1] + bv.y;
            o1.x = acc[mt][nt][2] + bv.x; o1.y = acc[mt][nt][3] + bv.y;
            if (epi == 0) {
                __half* Ch = (__half*)Cv;
                *(__half2*)(Ch + (size_t)r0 * N + ncol) = __floats2half2_rn(o0.x, o0.y);
                *(__half2*)(Ch + (size_t)r1 * N + ncol) = __floats2half2_rn(o1.x, o1.y);
            } else if (epi == 1) {
                __half* Ch = (__half*)Cv;
                *(__half2*)(Ch + (size_t)r0 * N + ncol) =
                    __floats2half2_rn(fmaxf(o0.x, 0.f), fmaxf(o0.y, 0.f));
                *(__half2*)(Ch + (size_t)r1 * N + ncol) =
                    __floats2half2_rn(fmaxf(o1.x, 0.f), fmaxf(o1.y, 0.f));
            } else {
                float* Cf = (float*)Cv;
                float2 rv0 = *(const float2*)(res + (size_t)r0 * N + ncol);
                float2 rv1 = *(const float2*)(res + (size_t)r1 * N + ncol);
                o0.x = (o0.x + rv0.x) * mk0; o0.y = (o0.y + rv0.y) * mk0;
                o1.x = (o1.x + rv1.x) * mk1; o1.y = (o1.y + rv1.y) * mk1;
                *(float2*)(Cf + (size_t)r0 * N + ncol) = o0;
                *(float2*)(Cf + (size_t)r1 * N + ncol) = o1;
            }
        }
    }
}

// ---------------- FP16 flash attention (mma m16n8k16, ldsm.trans V) ----------
// grid (S/128, H, B), 256 threads = 8 warps, each warp 16 q-rows. KT=32.
#define AQT 128
#define AKT 32
#define KSTR 72

__global__ __launch_bounds__(256)
void attn_f16_kernel(const __half* __restrict__ QKV, const int* __restrict__ npm,
                     __half* __restrict__ O)
{
    __shared__ __half Qs[AQT][KSTR];
    __shared__ __half Ks[2][AKT][KSTR];
    __shared__ __half Vs[2][AKT][KSTR];
    __shared__ int kmsi[2][AKT];

    const unsigned q_u = (unsigned)__cvta_generic_to_shared(Qs);
    const unsigned k_u = (unsigned)__cvta_generic_to_shared(Ks);
    const unsigned v_u = (unsigned)__cvta_generic_to_shared(Vs);
    const unsigned m_u = (unsigned)__cvta_generic_to_shared(kmsi);

    const int b = blockIdx.z, h = blockIdx.y, qt = blockIdx.x;
    const int tid  = threadIdx.x;
    const int lane = tid & 31;
    const int wq   = tid >> 5;        // 0..7
    const int g    = lane >> 2;
    const int cc   = lane & 3;
    const int l15  = lane & 15;
    const int lhi  = lane >> 4;
    const int wr   = wq * 16;

    const int RS = 3 * DD;
    const __half* Qbase = QKV + (size_t)(b * SS + qt * AQT) * RS + h * 64;
    const __half* Kb0   = QKV + (size_t)(b * SS) * RS + DD + h * 64;
    const __half* Vb0   = QKV + (size_t)(b * SS) * RS + 2 * DD + h * 64;

    #pragma unroll
    for (int i = tid; i < AQT * 8; i += 256) {
        int r = i >> 3, c = (i & 7) * 8;
        cp16(q_u + (unsigned)((r * KSTR + c) * 2), Qbase + (size_t)r * RS + c);
    }
    CP_COMMIT();

    auto load_kv = [&](int s, int kt) {
        const __half* kp = Kb0 + (size_t)(kt * AKT) * RS;
        const __half* vp = Vb0 + (size_t)(kt * AKT) * RS;
        {
            int i = tid;                     // AKT*8 = 256 chunks, 1 per thread
            int r = i >> 3, c = (i & 7) * 8;
            cp16(k_u + (unsigned)(((s * AKT + r) * KSTR + c) * 2), kp + (size_t)r * RS + c);
            cp16(v_u + (unsigned)(((s * AKT + r) * KSTR + c) * 2), vp + (size_t)r * RS + c);
        }
        if (tid < AKT) cp4(m_u + (unsigned)((s * AKT + tid) * 4),
                           npm + b * SS + kt * AKT + tid);
    };

    load_kv(0, 0); CP_COMMIT();

    float m0 = -1e30f, m1 = -1e30f, l0 = 0.f, l1 = 0.f;
    float o[8][4];
    #pragma unroll
    for (int nt = 0; nt < 8; nt++) {
        o[nt][0] = 0.f; o[nt][1] = 0.f; o[nt][2] = 0.f; o[nt][3] = 0.f;
    }

    const unsigned qf_off = (unsigned)(((wr + l15) * KSTR + lhi * 8) * 2);
    const int NKT = SS / AKT;

    for (int kt = 0; kt < NKT; kt++) {
        int st = kt & 1;
        if (kt + 1 < NKT) load_kv(st ^ 1, kt + 1);
        CP_COMMIT();
        CP_WAIT1();
        __syncthreads();

        float s[4][4];
        #pragma unroll
        for (int nt = 0; nt < 4; nt++) {
            s[nt][0] = 0.f; s[nt][1] = 0.f; s[nt][2] = 0.f; s[nt][3] = 0.f;
        }
        #pragma unroll
        for (int ks = 0; ks < 4; ks++) {
            unsigned a[4];
            ldsm4(a, q_u + qf_off + (unsigned)(ks * 32));
            #pragma unroll
            for (int bt = 0; bt < 2; bt++) {
                unsigned bfr[4];
                ldsm4(bfr, k_u + (unsigned)((((st * AKT + bt * 16 + l15) * KSTR + lhi * 8) * 2 + ks * 32)));
                {   unsigned bf[2] = { bfr[0], bfr[2] };
                    mma_f16(s[bt*2    ], a, bf); }
                {   unsigned bf[2] = { bfr[1], bfr[3] };
                    mma_f16(s[bt*2 + 1], a, bf); }
            }
        }

        #pragma unroll
        for (int nt = 0; nt < 4; nt++) {
            int k0i = kmsi[st][nt*8 + 2*cc];
            int k1i = kmsi[st][nt*8 + 2*cc + 1];
            s[nt][0] = k0i ? s[nt][0] * ATT_SCALE : -1e9f;
            s[nt][1] = k1i ? s[nt][1] * ATT_SCALE : -1e9f;
            s[nt][2] = k0i ? s[nt][2] * ATT_SCALE : -1e9f;
            s[nt][3] = k1i ? s[nt][3] * ATT_SCALE : -1e9f;
        }

        float tm0 = s[0][0], tm1 = s[0][2];
        #pragma unroll
        for (int nt = 0; nt < 4; nt++) {
            tm0 = fmaxf(tm0, fmaxf(s[nt][0], s[nt][1]));
            tm1 = fmaxf(tm1, fmaxf(s[nt][2], s[nt][3]));
        }
        tm0 = fmaxf(tm0, __shfl_xor_sync(0xffffffffu, tm0, 1));
        tm0 = fmaxf(tm0, __shfl_xor_sync(0xffffffffu, tm0, 2));
        tm1 = fmaxf(tm1, __shfl_xor_sync(0xffffffffu, tm1, 1));
        tm1 = fmaxf(tm1, __shfl_xor_sync(0xffffffffu, tm1, 2));
        float nm0 = fmaxf(m0, tm0), nm1 = fmaxf(m1, tm1);
        float f0 = __expf(m0 - nm0), f1 = __expf(m1 - nm1);

        float sum0 = 0.f, sum1 = 0.f;
        unsigned ap[2][4];
        #pragma unroll
        for (int nt = 0; nt < 4; nt++) {
            float p0 = __expf(s[nt][0] - nm0);
            float p1 = __expf(s[nt][1] - nm0);
            float p2 = __expf(s[nt][2] - nm1);
            float p3 = __expf(s[nt][3] - nm1);
            sum0 += p0 + p1;
            sum1 += p2 + p3;
            int ks = nt >> 1, hi = (nt & 1) * 2;
            ap[ks][hi    ] = packh2(p0, p1);
            ap[ks][hi + 1] = packh2(p2, p3);
        }
        sum0 += __shfl_xor_sync(0xffffffffu, sum0, 1);
        sum0 += __shfl_xor_sync(0xffffffffu, sum0, 2);
        sum1 += __shfl_xor_sync(0xffffffffu, sum1, 1);
        sum1 += __shfl_xor_sync(0xffffffffu, sum1, 2);
        l0 = l0 * f0 + sum0;
        l1 = l1 * f1 + sum1;
        m0 = nm0; m1 = nm1;

        #pragma unroll
        for (int nt = 0; nt < 8; nt++) {
            o[nt][0] *= f0; o[nt][1] *= f0;
            o[nt][2] *= f1; o[nt][3] *= f1;
        }

        #pragma unroll
        for (int ks = 0; ks < 2; ks++) {
            #pragma unroll
            for (int dkc = 0; dkc < 4; dkc++) {
                unsigned bfr[4];
                ldsm4t(bfr, v_u + (unsigned)((((st * AKT + ks * 16 + l15) * KSTR
                                               + dkc * 16 + lhi * 8) * 2)));
                {   unsigned bf[2] = { bfr[0], bfr[1] };
                    mma_f16(o[dkc*2    ], ap[ks], bf); }
                {   unsigned bf[2] = { bfr[2], bfr[3] };
                    mma_f16(o[dkc*2 + 1], ap[ks], bf); }
            }
        }
        __syncthreads();
    }

    float i0 = 1.f / l0, i1 = 1.f / l1;
    size_t r0 = (size_t)(b * SS + qt * AQT + wr + g) * DD + h * 64;
    size_t r1 = r0 + (size_t)8 * DD;
    #pragma unroll
    for (int nt = 0; nt < 8; nt++) {
        int ncol = nt * 8 + 2 * cc;
        *(__half2*)(O + r0 + ncol) = __floats2half2_rn(o[nt][0] * i0, o[nt][1] * i0);
        *(__half2*)(O + r1 + ncol) = __floats2half2_rn(o[nt][2] * i1, o[nt][3] * i1);
    }
}

// ---------------- host orchestration ----------------
extern "C" void kernel_launch(void* const* d_in, const int* in_sizes, int n_in,
                              void* d_out, int out_size)
{
    const float* embed = (const float*)d_in[0];
    const int*   npm   = (const int*)  d_in[1];
    const float* pe    = (const float*)d_in[2];
    const float* Wq    = (const float*)d_in[3];
    const float* bq    = (const float*)d_in[4];
    const float* Wk    = (const float*)d_in[5];
    const float* bk    = (const float*)d_in[6];
    const float* Wv    = (const float*)d_in[7];
    const float* bv    = (const float*)d_in[8];
    const float* Wo    = (const float*)d_in[9];
    const float* bo    = (const float*)d_in[10];
    const float* ln1g  = (const float*)d_in[11];
    const float* ln1b  = (const float*)d_in[12];
    const float* W1    = (const float*)d_in[13];
    const float* b1    = (const float*)d_in[14];
    const float* W2    = (const float*)d_in[15];
    const float* b2    = (const float*)d_in[16];
    const float* ln2g  = (const float*)d_in[17];
    const float* ln2b  = (const float*)d_in[18];
    const float* lnfg  = (const float*)d_in[19];
    const float* lnfb  = (const float*)d_in[20];

    float *x, *hh, *x1, *bqkv;
    __half *htf, *qkv, *ob, *ffb;
    __half *wqkvc, *woc, *w1c, *w2c;
    cudaGetSymbolAddress((void**)&x,    g_x);
    cudaGetSymbolAddress((void**)&hh,   g_h);
    cudaGetSymbolAddress((void**)&htf,  g_htf);
    cudaGetSymbolAddress((void**)&x1,   g_x1);
    cudaGetSymbolAddress((void**)&qkv,  g_qkv);
    cudaGetSymbolAddress((void**)&ob,   g_o);
    cudaGetSymbolAddress((void**)&ffb,  g_ff);
    cudaGetSymbolAddress((void**)&wqkvc, g_wqkvc);
    cudaGetSymbolAddress((void**)&woc,  g_woc);
    cudaGetSymbolAddress((void**)&w1c,  g_w1c);
    cudaGetSymbolAddress((void**)&w2c,  g_w2c);
    cudaGetSymbolAddress((void**)&bqkv, g_bqkv);

    cudaFuncSetAttribute(mma_gemm_kernel,
                         cudaFuncAttributeMaxDynamicSharedMemorySize,
                         GEMM_SMEM_BYTES);

    // weight prep
    {
        dim3 blk(32, 8);
        size_t qkvLS = (size_t)3 * DD * DD;
        h16conv_t_kernel<<<dim3(DD/32, DD/32, LYR), blk>>>(Wq, wqkvc, DD, DD, qkvLS, 0);
        h16conv_t_kernel<<<dim3(DD/32, DD/32, LYR), blk>>>(Wk, wqkvc, DD, DD, qkvLS, DD);
        h16conv_t_kernel<<<dim3(DD/32, DD/32, LYR), blk>>>(Wv, wqkvc, DD, DD, qkvLS, 2*DD);
        h16conv_t_kernel<<<dim3(DD/32, DD/32, LYR), blk>>>(Wo, woc, DD, DD, (size_t)DD*DD, 0);
        h16conv_t_kernel<<<dim3(FF/32, DD/32, LYR), blk>>>(W1, w1c, DD, FF, (size_t)DD*FF, 0);
        h16conv_t_kernel<<<dim3(DD/32, FF/32, LYR), blk>>>(W2, w2c, FF, DD, (size_t)FF*DD, 0);
        int nb = LYR * 3 * DD;
        bias_cat_kernel<<<(nb + 255) / 256, 256>>>(bq, bk, bv, bqkv);
    }

    {
        int tot4 = MM * DD / 4;
        add_pe_kernel<<<(tot4 + 255) / 256, 256>>>(embed, pe, x);
    }

    dim3 gQKV(3 * DD / BN, MM / BM);  // (24, 32)
    dim3 gD(DD / BN, MM / BM);        // (8, 32)
    dim3 gF(FF / BN, MM / BM);        // (32, 32)
    dim3 gAttn(SS / AQT, HH, BB);     // (8, 16, 4)

    for (int l = 0; l < LYR; l++) {
        const __half* wqkv_l = wqkvc + (size_t)l * 3 * DD * DD;
        const __half* wo = woc + (size_t)l * DD * DD;
        const __half* w1 = w1c + (size_t)l * DD * FF;
        const __half* w2 = w2c + (size_t)l * FF * DD;
        const float* lbqkv = bqkv + (size_t)l * 3 * DD;
        const float* lbo = bo + (size_t)l * DD;
        const float* lb1 = b1 + (size_t)l * FF;
        const float* lb2 = b2 + (size_t)l * DD;

        ln_kernel<<<MM, 256>>>(x, ln1g + (size_t)l * DD, ln1b + (size_t)l * DD, hh, htf);
        mma_gemm_kernel<<<gQKV, 256, GEMM_SMEM_BYTES>>>(htf, wqkv_l, lbqkv, nullptr, nullptr, qkv, MM, 3*DD, DD, 0);
        attn_f16_kernel<<<gAttn, 256>>>(qkv, npm, ob);
        mma_gemm_kernel<<<gD, 256, GEMM_SMEM_BYTES>>>(ob, wo, lbo, hh, npm, x1, MM, DD, DD, 2);
        ln_kernel<<<MM, 256>>>(x1, ln2g + (size_t)l * DD, ln2b + (size_t)l * DD, hh, htf);
        mma_gemm_kernel<<<gF, 256, GEMM_SMEM_BYTES>>>(htf, w1, lb1, nullptr, nullptr, ffb, MM, FF, DD, 1);
        mma_gemm_kernel<<<gD, 256, GEMM_SMEM_BYTES>>>(ffb, w2, lb2, hh, npm, x, MM, DD, FF, 2);
    }

    ln_kernel<<<MM, 256>>>(x, lnfg, lnfb, (float*)d_out, nullptr);
}

// round 15
// speedup vs baseline: 1.0325x; 1.0231x over previous
#include <cuda_runtime.h>
#include <cuda_fp16.h>
#include <math.h>
#include <stdint.h>

// Problem constants
#define LYR 6
#define BB  4
#define SS  1024
#define DD  1024
#define HH  16
#define DKK 64
#define FF  4096
#define MM  (BB*SS)          // 4096 rows
#define ATT_SCALE 0.125f     // 1/sqrt(64)
#define LN_EPS 1e-6f

// ---------------- scratch buffers (device globals; no allocation) -------------
__device__ float  g_x [MM*DD];
__device__ float  g_h [MM*DD];
__device__ __half g_htf[MM*DD];     // fp16 LN output (GEMM A operand)
__device__ float  g_x1[MM*DD];
__device__ __half g_qkv[MM*3*DD];   // fused QKV output
__device__ __half g_o [MM*DD];      // attn out, fp16
__device__ __half g_ff[MM*FF];      // relu out, fp16
// pre-converted + TRANSPOSED weights: Bt[n][k] = fp16(W[k][n])
__device__ __half g_wqkvc[LYR*3*DD*DD];
__device__ __half g_woc[LYR*DD*DD];
__device__ __half g_w1c[LYR*DD*FF];
__device__ __half g_w2c[LYR*FF*DD];
__device__ float  g_bqkv[LYR*3*DD];

// ---------------- helpers ----------------
__device__ __forceinline__ void mma_f16(float c[4], const unsigned a[4], const unsigned b[2]) {
    asm volatile("mma.sync.aligned.m16n8k16.row.col.f32.f16.f16.f32 "
        "{%0,%1,%2,%3}, {%4,%5,%6,%7}, {%8,%9}, {%0,%1,%2,%3};"
        : "+f"(c[0]), "+f"(c[1]), "+f"(c[2]), "+f"(c[3])
        : "r"(a[0]), "r"(a[1]), "r"(a[2]), "r"(a[3]), "r"(b[0]), "r"(b[1]));
}

__device__ __forceinline__ void ldsm4(unsigned r[4], unsigned addr) {
    asm volatile("ldmatrix.sync.aligned.m8n8.x4.shared.b16 {%0,%1,%2,%3}, [%4];"
        : "=r"(r[0]), "=r"(r[1]), "=r"(r[2]), "=r"(r[3]) : "r"(addr));
}

__device__ __forceinline__ void ldsm4t(unsigned r[4], unsigned addr) {
    asm volatile("ldmatrix.sync.aligned.m8n8.x4.trans.shared.b16 {%0,%1,%2,%3}, [%4];"
        : "=r"(r[0]), "=r"(r[1]), "=r"(r[2]), "=r"(r[3]) : "r"(addr));
}

__device__ __forceinline__ void cp16(unsigned dst, const void* src) {
    asm volatile("cp.async.cg.shared.global [%0], [%1], 16;" :: "r"(dst), "l"(src));
}
__device__ __forceinline__ void cp4(unsigned dst, const void* src) {
    asm volatile("cp.async.ca.shared.global [%0], [%1], 4;" :: "r"(dst), "l"(src));
}
#define CP_COMMIT() asm volatile("cp.async.commit_group;" ::: "memory")
#define CP_WAIT2()  asm volatile("cp.async.wait_group 2;" ::: "memory")
#define CP_WAIT1()  asm volatile("cp.async.wait_group 1;" ::: "memory")

__device__ __forceinline__ unsigned packh2(float a, float b) {
    __half2 h = __floats2half2_rn(a, b);
    return *(unsigned*)&h;
}

// ---------------- weight prep: dst[n][k] = fp16(src[k][n]) -------------------
// 64(k) x 32(n) tile; store phase emits half2 (full 128B store lines).
__global__ void h16conv_t_kernel(const float* __restrict__ src,
                                 __half* __restrict__ dst, int K, int N,
                                 size_t dstLayerStride, int rowOff)
{
    __shared__ float t[64][33];
    int l = blockIdx.z;
    const float* s = src + (size_t)l * K * N;
    __half* d = dst + (size_t)l * dstLayerStride + (size_t)rowOff * K;
    int n0 = blockIdx.x * 32, k0 = blockIdx.y * 64;
    int tx = threadIdx.x, ty = threadIdx.y;   // 32 x 8
    #pragma unroll
    for (int i = 0; i < 64; i += 8)
        t[ty + i][tx] = s[(size_t)(k0 + ty + i) * N + n0 + tx];
    __syncthreads();
    #pragma unroll
    for (int i = 0; i < 32; i += 8) {
        int n = ty + i;
        __half2 h = __floats2half2_rn(t[2 * tx][n], t[2 * tx + 1][n]);
        *(__half2*)(d + (size_t)(n0 + n) * K + k0 + 2 * tx) = h;
    }
}

// ---------------- bias concat for fused QKV ----------------------------------
__global__ void bias_cat_kernel(const float* __restrict__ bq,
                                const float* __restrict__ bk,
                                const float* __restrict__ bv,
                                float* __restrict__ out)
{
    int i = blockIdx.x * blockDim.x + threadIdx.x;
    if (i >= LYR * 3 * DD) return;
    int l = i / (3 * DD), j = i % (3 * DD);
    float v = (j < DD) ? bq[l * DD + j]
            : (j < 2 * DD) ? bk[l * DD + j - DD]
            : bv[l * DD + j - 2 * DD];
    out[i] = v;
}

// ---------------- PE add ----------------
__global__ void add_pe_kernel(const float* __restrict__ embed,
                              const float* __restrict__ pe,
                              float* __restrict__ x)
{
    int i = blockIdx.x * blockDim.x + threadIdx.x;
    const int TOT4 = MM * DD / 4;
    if (i >= TOT4) return;
    int pe4 = i % (SS * DD / 4);
    float4 e = ((const float4*)embed)[i];
    float4 p = ((const float4*)pe)[pe4];
    float4 r; r.x = e.x + p.x; r.y = e.y + p.y; r.z = e.z + p.z; r.w = e.w + p.w;
    ((float4*)x)[i] = r;
}

// ---------------- LayerNorm (dual output: fp32 + fp16) -----------------------
__global__ void ln_kernel(const float* __restrict__ x,
                          const float* __restrict__ g,
                          const float* __restrict__ beta,
                          float* __restrict__ y,
                          __half* __restrict__ ytf)
{
    __shared__ float shm[32];
    __shared__ float s_mu, s_rstd;
    int row = blockIdx.x;
    int t   = threadIdx.x;
    const float4* xr = (const float4*)(x + (size_t)row * DD);
    float4 v = xr[t];
    float s = v.x + v.y + v.z + v.w;
    #pragma unroll
    for (int o = 16; o; o >>= 1) s += __shfl_xor_sync(0xffffffffu, s, o);
    if ((t & 31) == 0) shm[t >> 5] = s;
    __syncthreads();
    if (t < 32) {
        float tot = (t < 8) ? shm[t] : 0.f;
        #pragma unroll
        for (int o = 4; o; o >>= 1) tot += __shfl_xor_sync(0xffffffffu, tot, o);
        if (t == 0) s_mu = tot * (1.0f / DD);
    }
    __syncthreads();
    float mu = s_mu;
    float d0 = v.x - mu, d1 = v.y - mu, d2 = v.z - mu, d3 = v.w - mu;
    float s2 = d0*d0 + d1*d1 + d2*d2 + d3*d3;
    #pragma unroll
    for (int o = 16; o; o >>= 1) s2 += __shfl_xor_sync(0xffffffffu, s2, o);
    if ((t & 31) == 0) shm[t >> 5] = s2;
    __syncthreads();
    if (t < 32) {
        float tot = (t < 8) ? shm[t] : 0.f;
        #pragma unroll
        for (int o = 4; o; o >>= 1) tot += __shfl_xor_sync(0xffffffffu, tot, o);
        if (t == 0) s_rstd = rsqrtf(tot * (1.0f / DD) + LN_EPS);
    }
    __syncthreads();
    float rstd = s_rstd;
    float4 gg = ((const float4*)g)[t];
    float4 bb = ((const float4*)beta)[t];
    float4 out;
    out.x = d0 * rstd * gg.x + bb.x;
    out.y = d1 * rstd * gg.y + bb.y;
    out.z = d2 * rstd * gg.z + bb.z;
    out.w = d3 * rstd * gg.w + bb.w;
    ((float4*)(y + (size_t)row * DD))[t] = out;
    if (ytf) {
        __half2* yh = (__half2*)(ytf + (size_t)row * DD);
        yh[2*t    ] = __floats2half2_rn(out.x, out.y);
        yh[2*t + 1] = __floats2half2_rn(out.z, out.w);
    }
}

// ---------------- FP16 GEMM 128x128 (mma m16n8k16), 4-stage cp.async ---------
#define BM 128
#define BN 128
#define BKH 32
#define STAGES 4
#define STRH 40
#define T_STG (BM*STRH)
#define GEMM_SMEM_BYTES (STAGES * 2 * T_STG * 2)   // 81920

__global__ __launch_bounds__(256, 2)
void mma_gemm_kernel(const __half* __restrict__ A, const __half* __restrict__ Bt,
                     const float* __restrict__ bias, const float* __restrict__ res,
                     const int* __restrict__ mask, void* __restrict__ Cv,
                     int M, int N, int K, int epi)
{
    extern __shared__ __half smemh[];
    __half* Asm = smemh;
    __half* Bsm = smemh + STAGES * T_STG;
    const unsigned a_u = (unsigned)__cvta_generic_to_shared(Asm);
    const unsigned b_u = (unsigned)__cvta_generic_to_shared(Bsm);

    const int tid  = threadIdx.x;
    const int lane = tid & 31;
    const int wrp  = tid >> 5;
    const int wm   = wrp >> 2;
    const int wn   = wrp & 3;
    const int l15  = lane & 15;
    const int lhi  = lane >> 4;
    const int g    = lane >> 2;
    const int cc   = lane & 3;

    const int brow = blockIdx.y * BM;
    const int bcol = blockIdx.x * BN;

    const int s_r = tid >> 1, s_c = (tid & 1) * 16;
    const __half* Ag = A  + (size_t)(brow + s_r) * K + s_c;
    const __half* Bg = Bt + (size_t)(bcol + s_r) * K + s_c;

    const int NK = K / BKH;

    auto load_stage = [&](int s, int kt) {
        const __half* ag = Ag + kt * BKH;
        const __half* bg = Bg + kt * BKH;
        unsigned d = (unsigned)((s * T_STG + s_r * STRH + s_c) * 2);
        cp16(a_u + d, ag); cp16(a_u + d + 16, ag + 8);
        cp16(b_u + d, bg); cp16(b_u + d + 16, bg + 8);
    };

    float acc[4][4][4];
    #pragma unroll
    for (int i = 0; i < 4; i++)
        #pragma unroll
        for (int j = 0; j < 4; j++) {
            acc[i][j][0] = 0.f; acc[i][j][1] = 0.f;
            acc[i][j][2] = 0.f; acc[i][j][3] = 0.f;
        }

    load_stage(0, 0); CP_COMMIT();
    load_stage(1, 1); CP_COMMIT();
    load_stage(2, 2); CP_COMMIT();

    const unsigned a_frag_off = (unsigned)(((wm * 64 + l15) * STRH + lhi * 8) * 2);
    const unsigned b_frag_off = (unsigned)(((wn * 32 + l15) * STRH + lhi * 8) * 2);

    int cur = 0;
    for (int kt = 0; kt < NK; kt++) {
        CP_WAIT2();
        __syncthreads();

        if (kt + 3 < NK) load_stage((kt + 3) & 3, kt + 3);
        CP_COMMIT();

        const unsigned abase = a_u + (unsigned)(cur * T_STG * 2) + a_frag_off;
        const unsigned bbase = b_u + (unsigned)(cur * T_STG * 2) + b_frag_off;

        #pragma unroll
        for (int ks = 0; ks < 2; ks++) {
            unsigned a[4][4], b[2][4];
            #pragma unroll
            for (int mt = 0; mt < 4; mt++)
                ldsm4(a[mt], abase + (unsigned)(mt * 16 * STRH * 2 + ks * 32));
            #pragma unroll
            for (int bt = 0; bt < 2; bt++)
                ldsm4(b[bt], bbase + (unsigned)(bt * 16 * STRH * 2 + ks * 32));

            #pragma unroll
            for (int mt = 0; mt < 4; mt++) {
                {   unsigned bf[2] = { b[0][0], b[0][2] };
                    mma_f16(acc[mt][0], a[mt], bf); }
                {   unsigned bf[2] = { b[0][1], b[0][3] };
                    mma_f16(acc[mt][1], a[mt], bf); }
                {   unsigned bf[2] = { b[1][0], b[1][2] };
                    mma_f16(acc[mt][2], a[mt], bf); }
                {   unsigned bf[2] = { b[1][1], b[1][3] };
                    mma_f16(acc[mt][3], a[mt], bf); }
            }
        }
        cur = (cur + 1) & 3;
    }

    // ---- epilogue ----
    #pragma unroll
    for (int mt = 0; mt < 4; mt++) {
        int r0 = brow + wm * 64 + mt * 16 + g;
        int r1 = r0 + 8;
        float mk0 = 1.f, mk1 = 1.f;
        if (epi == 2) {
            mk0 = mask[r0] ? 1.f : 0.f;
            mk1 = mask[r1] ? 1.f : 0.f;
        }
        #pragma unroll
        for (int nt = 0; nt < 4; nt++) {
            int ncol = bcol + wn * 32 + nt * 8 + cc * 2;
            float2 bv = *(const float2*)(bias + ncol);
            float2 o0, o1;
            o0.x = acc[mt][nt][0] + bv.x; o0.y = acc[mt][nt][1] + bv.y;
            o1.x = acc[mt][nt][2] + bv.x; o1.y = acc[mt][nt][3] + bv.y;
            if (epi == 0) {
                __half* Ch = (__half*)Cv;
                *(__half2*)(Ch + (size_t)r0 * N + ncol) = __floats2half2_rn(o0.x, o0.y);
                *(__half2*)(Ch + (size_t)r1 * N + ncol) = __floats2half2_rn(o1.x, o1.y);
            } else if (epi == 1) {
                __half* Ch = (__half*)Cv;
                *(__half2*)(Ch + (size_t)r0 * N + ncol) =
                    __floats2half2_rn(fmaxf(o0.x, 0.f), fmaxf(o0.y, 0.f));
                *(__half2*)(Ch + (size_t)r1 * N + ncol) =
                    __floats2half2_rn(fmaxf(o1.x, 0.f), fmaxf(o1.y, 0.f));
            } else {
                float* Cf = (float*)Cv;
                float2 rv0 = *(const float2*)(res + (size_t)r0 * N + ncol);
                float2 rv1 = *(const float2*)(res + (size_t)r1 * N + ncol);
                o0.x = (o0.x + rv0.x) * mk0; o0.y = (o0.y + rv0.y) * mk0;
                o1.x = (o1.x + rv1.x) * mk1; o1.y = (o1.y + rv1.y) * mk1;
                *(float2*)(Cf + (size_t)r0 * N + ncol) = o0;
                *(float2*)(Cf + (size_t)r1 * N + ncol) = o1;
            }
        }
    }
}

// ---------------- FP16 flash attention (mma m16n8k16, ldsm.trans V) ----------
// grid (S/64, H, B), 128 threads = 4 warps. KT=32, double-buffered cp.async.
#define AQT 64
#define AKT 32
#define KSTR 72

__global__ __launch_bounds__(128)
void attn_f16_kernel(const __half* __restrict__ QKV, const int* __restrict__ npm,
                     __half* __restrict__ O)
{
    __shared__ __half Qs[AQT][KSTR];
    __shared__ __half Ks[2][AKT][KSTR];
    __shared__ __half Vs[2][AKT][KSTR];
    __shared__ int kmsi[2][AKT];

    const unsigned q_u = (unsigned)__cvta_generic_to_shared(Qs);
    const unsigned k_u = (unsigned)__cvta_generic_to_shared(Ks);
    const unsigned v_u = (unsigned)__cvta_generic_to_shared(Vs);
    const unsigned m_u = (unsigned)__cvta_generic_to_shared(kmsi);

    const int b = blockIdx.z, h = blockIdx.y, qt = blockIdx.x;
    const int tid  = threadIdx.x;
    const int lane = tid & 31;
    const int wq   = tid >> 5;
    const int g    = lane >> 2;
    const int cc   = lane & 3;
    const int l15  = lane & 15;
    const int lhi  = lane >> 4;
    const int wr   = wq * 16;

    const int RS = 3 * DD;
    const __half* Qbase = QKV + (size_t)(b * SS + qt * AQT) * RS + h * 64;
    const __half* Kb0   = QKV + (size_t)(b * SS) * RS + DD + h * 64;
    const __half* Vb0   = QKV + (size_t)(b * SS) * RS + 2 * DD + h * 64;

    #pragma unroll
    for (int i = tid; i < AQT * 8; i += 128) {
        int r = i >> 3, c = (i & 7) * 8;
        cp16(q_u + (unsigned)((r * KSTR + c) * 2), Qbase + (size_t)r * RS + c);
    }
    CP_COMMIT();

    auto load_kv = [&](int s, int kt) {
        const __half* kp = Kb0 + (size_t)(kt * AKT) * RS;
        const __half* vp = Vb0 + (size_t)(kt * AKT) * RS;
        #pragma unroll
        for (int i = tid; i < AKT * 8; i += 128) {
            int r = i >> 3, c = (i & 7) * 8;
            cp16(k_u + (unsigned)(((s * AKT + r) * KSTR + c) * 2), kp + (size_t)r * RS + c);
            cp16(v_u + (unsigned)(((s * AKT + r) * KSTR + c) * 2), vp + (size_t)r * RS + c);
        }
        if (tid < AKT) cp4(m_u + (unsigned)((s * AKT + tid) * 4),
                           npm + b * SS + kt * AKT + tid);
    };

    load_kv(0, 0); CP_COMMIT();

    float m0 = -1e30f, m1 = -1e30f, l0 = 0.f, l1 = 0.f;
    float o[8][4];
    #pragma unroll
    for (int nt = 0; nt < 8; nt++) {
        o[nt][0] = 0.f; o[nt][1] = 0.f; o[nt][2] = 0.f; o[nt][3] = 0.f;
    }

    const unsigned qf_off = (unsigned)(((wr + l15) * KSTR + lhi * 8) * 2);
    const int NKT = SS / AKT;

    for (int kt = 0; kt < NKT; kt++) {
        int st = kt & 1;
        if (kt + 1 < NKT) load_kv(st ^ 1, kt + 1);
        CP_COMMIT();
        CP_WAIT1();
        __syncthreads();

        float s[4][4];
        #pragma unroll
        for (int nt = 0; nt < 4; nt++) {
            s[nt][0] = 0.f; s[nt][1] = 0.f; s[nt][2] = 0.f; s[nt][3] = 0.f;
        }
        #pragma unroll
        for (int ks = 0; ks < 4; ks++) {
            unsigned a[4];
            ldsm4(a, q_u + qf_off + (unsigned)(ks * 32));
            #pragma unroll
            for (int bt = 0; bt < 2; bt++) {
                unsigned bfr[4];
                ldsm4(bfr, k_u + (unsigned)((((st * AKT + bt * 16 + l15) * KSTR + lhi * 8) * 2 + ks * 32)));
                {   unsigned bf[2] = { bfr[0], bfr[2] };
                    mma_f16(s[bt*2    ], a, bf); }
                {   unsigned bf[2] = { bfr[1], bfr[3] };
                    mma_f16(s[bt*2 + 1], a, bf); }
            }
        }

        #pragma unroll
        for (int nt = 0; nt < 4; nt++) {
            int k0i = kmsi[st][nt*8 + 2*cc];
            int k1i = kmsi[st][nt*8 + 2*cc + 1];
            s[nt][0] = k0i ? s[nt][0] * ATT_SCALE : -1e9f;
            s[nt][1] = k1i ? s[nt][1] * ATT_SCALE : -1e9f;
            s[nt][2] = k0i ? s[nt][2] * ATT_SCALE : -1e9f;
            s[nt][3] = k1i ? s[nt][3] * ATT_SCALE : -1e9f;
        }

        float tm0 = s[0][0], tm1 = s[0][2];
        #pragma unroll
        for (int nt = 0; nt < 4; nt++) {
            tm0 = fmaxf(tm0, fmaxf(s[nt][0], s[nt][1]));
            tm1 = fmaxf(tm1, fmaxf(s[nt][2], s[nt][3]));
        }
        tm0 = fmaxf(tm0, __shfl_xor_sync(0xffffffffu, tm0, 1));
        tm0 = fmaxf(tm0, __shfl_xor_sync(0xffffffffu, tm0, 2));
        tm1 = fmaxf(tm1, __shfl_xor_sync(0xffffffffu, tm1, 1));
        tm1 = fmaxf(tm1, __shfl_xor_sync(0xffffffffu, tm1, 2));
        float nm0 = fmaxf(m0, tm0), nm1 = fmaxf(m1, tm1);
        float f0 = __expf(m0 - nm0), f1 = __expf(m1 - nm1);

        float sum0 = 0.f, sum1 = 0.f;
        unsigned ap[2][4];
        #pragma unroll
        for (int nt = 0; nt < 4; nt++) {
            float p0 = __expf(s[nt][0] - nm0);
            float p1 = __expf(s[nt][1] - nm0);
            float p2 = __expf(s[nt][2] - nm1);
            float p3 = __expf(s[nt][3] - nm1);
            sum0 += p0 + p1;
            sum1 += p2 + p3;
            int ks = nt >> 1, hi = (nt & 1) * 2;
            ap[ks][hi    ] = packh2(p0, p1);
            ap[ks][hi + 1] = packh2(p2, p3);
        }
        sum0 += __shfl_xor_sync(0xffffffffu, sum0, 1);
        sum0 += __shfl_xor_sync(0xffffffffu, sum0, 2);
        sum1 += __shfl_xor_sync(0xffffffffu, sum1, 1);
        sum1 += __shfl_xor_sync(0xffffffffu, sum1, 2);
        l0 = l0 * f0 + sum0;
        l1 = l1 * f1 + sum1;
        m0 = nm0; m1 = nm1;

        #pragma unroll
        for (int nt = 0; nt < 8; nt++) {
            o[nt][0] *= f0; o[nt][1] *= f0;
            o[nt][2] *= f1; o[nt][3] *= f1;
        }

        #pragma unroll
        for (int ks = 0; ks < 2; ks++) {
            #pragma unroll
            for (int dkc = 0; dkc < 4; dkc++) {
                unsigned bfr[4];
                ldsm4t(bfr, v_u + (unsigned)((((st * AKT + ks * 16 + l15) * KSTR
                                               + dkc * 16 + lhi * 8) * 2)));
                {   unsigned bf[2] = { bfr[0], bfr[1] };
                    mma_f16(o[dkc*2    ], ap[ks], bf); }
                {   unsigned bf[2] = { bfr[2], bfr[3] };
                    mma_f16(o[dkc*2 + 1], ap[ks], bf); }
            }
        }
        __syncthreads();
    }

    float i0 = 1.f / l0, i1 = 1.f / l1;
    size_t r0 = (size_t)(b * SS + qt * AQT + wr + g) * DD + h * 64;
    size_t r1 = r0 + (size_t)8 * DD;
    #pragma unroll
    for (int nt = 0; nt < 8; nt++) {
        int ncol = nt * 8 + 2 * cc;
        *(__half2*)(O + r0 + ncol) = __floats2half2_rn(o[nt][0] * i0, o[nt][1] * i0);
        *(__half2*)(O + r1 + ncol) = __floats2half2_rn(o[nt][2] * i1, o[nt][3] * i1);
    }
}

// ---------------- host orchestration ----------------
extern "C" void kernel_launch(void* const* d_in, const int* in_sizes, int n_in,
                              void* d_out, int out_size)
{
    const float* embed = (const float*)d_in[0];
    const int*   npm   = (const int*)  d_in[1];
    const float* pe    = (const float*)d_in[2];
    const float* Wq    = (const float*)d_in[3];
    const float* bq    = (const float*)d_in[4];
    const float* Wk    = (const float*)d_in[5];
    const float* bk    = (const float*)d_in[6];
    const float* Wv    = (const float*)d_in[7];
    const float* bv    = (const float*)d_in[8];
    const float* Wo    = (const float*)d_in[9];
    const float* bo    = (const float*)d_in[10];
    const float* ln1g  = (const float*)d_in[11];
    const float* ln1b  = (const float*)d_in[12];
    const float* W1    = (const float*)d_in[13];
    const float* b1    = (const float*)d_in[14];
    const float* W2    = (const float*)d_in[15];
    const float* b2    = (const float*)d_in[16];
    const float* ln2g  = (const float*)d_in[17];
    const float* ln2b  = (const float*)d_in[18];
    const float* lnfg  = (const float*)d_in[19];
    const float* lnfb  = (const float*)d_in[20];

    float *x, *hh, *x1, *bqkv;
    __half *htf, *qkv, *ob, *ffb;
    __half *wqkvc, *woc, *w1c, *w2c;
    cudaGetSymbolAddress((void**)&x,    g_x);
    cudaGetSymbolAddress((void**)&hh,   g_h);
    cudaGetSymbolAddress((void**)&htf,  g_htf);
    cudaGetSymbolAddress((void**)&x1,   g_x1);
    cudaGetSymbolAddress((void**)&qkv,  g_qkv);
    cudaGetSymbolAddress((void**)&ob,   g_o);
    cudaGetSymbolAddress((void**)&ffb,  g_ff);
    cudaGetSymbolAddress((void**)&wqkvc, g_wqkvc);
    cudaGetSymbolAddress((void**)&woc,  g_woc);
    cudaGetSymbolAddress((void**)&w1c,  g_w1c);
    cudaGetSymbolAddress((void**)&w2c,  g_w2c);
    cudaGetSymbolAddress((void**)&bqkv, g_bqkv);

    cudaFuncSetAttribute(mma_gemm_kernel,
                         cudaFuncAttributeMaxDynamicSharedMemorySize,
                         GEMM_SMEM_BYTES);

    // weight prep (64x32 tiles, half2 stores)
    {
        dim3 blk(32, 8);
        size_t qkvLS = (size_t)3 * DD * DD;
        h16conv_t_kernel<<<dim3(DD/32, DD/64, LYR), blk>>>(Wq, wqkvc, DD, DD, qkvLS, 0);
        h16conv_t_kernel<<<dim3(DD/32, DD/64, LYR), blk>>>(Wk, wqkvc, DD, DD, qkvLS, DD);
        h16conv_t_kernel<<<dim3(DD/32, DD/64, LYR), blk>>>(Wv, wqkvc, DD, DD, qkvLS, 2*DD);
        h16conv_t_kernel<<<dim3(DD/32, DD/64, LYR), blk>>>(Wo, woc, DD, DD, (size_t)DD*DD, 0);
        h16conv_t_kernel<<<dim3(FF/32, DD/64, LYR), blk>>>(W1, w1c, DD, FF, (size_t)DD*FF, 0);
        h16conv_t_kernel<<<dim3(DD/32, FF/64, LYR), blk>>>(W2, w2c, FF, DD, (size_t)FF*DD, 0);
        int nb = LYR * 3 * DD;
        bias_cat_kernel<<<(nb + 255) / 256, 256>>>(bq, bk, bv, bqkv);
    }

    {
        int tot4 = MM * DD / 4;
        add_pe_kernel<<<(tot4 + 255) / 256, 256>>>(embed, pe, x);
    }

    dim3 gQKV(3 * DD / BN, MM / BM);  // (24, 32)
    dim3 gD(DD / BN, MM / BM);        // (8, 32)
    dim3 gF(FF / BN, MM / BM);        // (32, 32)
    dim3 gAttn(SS / AQT, HH, BB);     // (16, 16, 4)

    for (int l = 0; l < LYR; l++) {
        const __half* wqkv_l = wqkvc + (size_t)l * 3 * DD * DD;
        const __half* wo = woc + (size_t)l * DD * DD;
        const __half* w1 = w1c + (size_t)l * DD * FF;
        const __half* w2 = w2c + (size_t)l * FF * DD;
        const float* lbqkv = bqkv + (size_t)l * 3 * DD;
        const float* lbo = bo + (size_t)l * DD;
        const float* lb1 = b1 + (size_t)l * FF;
        const float* lb2 = b2 + (size_t)l * DD;

        ln_kernel<<<MM, 256>>>(x, ln1g + (size_t)l * DD, ln1b + (size_t)l * DD, hh, htf);
        mma_gemm_kernel<<<gQKV, 256, GEMM_SMEM_BYTES>>>(htf, wqkv_l, lbqkv, nullptr, nullptr, qkv, MM, 3*DD, DD, 0);
        attn_f16_kernel<<<gAttn, 128>>>(qkv, npm, ob);
        mma_gemm_kernel<<<gD, 256, GEMM_SMEM_BYTES>>>(ob, wo, lbo, hh, npm, x1, MM, DD, DD, 2);
        ln_kernel<<<MM, 256>>>(x1, ln2g + (size_t)l * DD, ln2b + (size_t)l * DD, hh, htf);
        mma_gemm_kernel<<<gF, 256, GEMM_SMEM_BYTES>>>(htf, w1, lb1, nullptr, nullptr, ffb, MM, FF, DD, 1);
        mma_gemm_kernel<<<gD, 256, GEMM_SMEM_BYTES>>>(ffb, w2, lb2, hh, npm, x, MM, DD, FF, 2);
    }

    ln_kernel<<<MM, 256>>>(x, lnfg, lnfb, (float*)d_out, nullptr);
}